// round 5
// baseline (speedup 1.0000x reference)
#include <cuda_runtime.h>
#include <math.h>
#include <float.h>
#include <stdint.h>

// Problem constants (fixed by the dataset)
#define S_   7
#define B_   2
#define C_   80
#define NGT  32
#define BT_  8192
#define CELLF 90                    // B*5 + C
#define ITEMF (S_ * S_ * CELLF)     // 4410 floats per batch item
#define NCELLS (BT_ * S_ * S_)      // 401408
#define NBOX   (NCELLS * B_)        // 802816
#define NGTS   (BT_ * NGT)          // 262144

#define NTHR 256
#define ITEMS_PER_BLOCK 8
#define PAIRS (ITEMS_PER_BLOCK / 2)
#define NBLK (BT_ / ITEMS_PER_BLOCK)    // 1024
#define NWARP (NTHR / 32)
#define PAIR_FLOATS (2 * ITEMF)          // 8820
#define PAIR_BYTES  (PAIR_FLOATS * 4)    // 35280 (16B multiple)

// Per-block partial sums: [coord, obj, posconf_sq, cls, npos, noobj_all]
__device__ double g_part[NBLK][6];
__device__ unsigned int g_count = 0;

__device__ __forceinline__ float sigmoidf_(float x) {
    return 1.0f / (1.0f + __expf(-x));
}

__device__ __forceinline__ uint32_t smem_u32(const void* p) {
    uint32_t a;
    asm("{ .reg .u64 t; cvta.to.shared.u64 t, %1; cvt.u32.u64 %0, t; }"
        : "=r"(a) : "l"(p));
    return a;
}

__global__ void __launch_bounds__(NTHR, 4)
yolo_loss_stream(const float* __restrict__ preds,
                 const float* __restrict__ gt_boxes,
                 const int* __restrict__ gt_labels,
                 const unsigned char* __restrict__ gt_valid,
                 float* __restrict__ out)
{
    __shared__ float4 spred4[PAIR_FLOATS / 4];   // 35280 B, 16B aligned
    __shared__ float4 sbox[64];
    __shared__ int    slab[64];
    __shared__ float  svalid[64];
    __shared__ unsigned long long mbar;
    __shared__ double shred[NWARP][6];

    float* spred = (float*)spred4;
    const int tid  = threadIdx.x;
    const int lane = tid & 31;
    const int wid  = tid >> 5;
    const unsigned FULL = 0xffffffffu;

    const uint32_t mbar_a  = smem_u32(&mbar);
    const uint32_t spred_a = smem_u32(spred4);

    if (tid == 0) {
        asm volatile("mbarrier.init.shared.b64 [%0], %1;"
                     :: "r"(mbar_a), "r"(1u) : "memory");
    }
    __syncthreads();

    float coord = 0.f, obj = 0.f, posconf = 0.f, clsl = 0.f, npos = 0.f, noobj = 0.f;

    const int item0 = blockIdx.x * ITEMS_PER_BLOCK;
    const int gt_l  = tid >> 3;       // 0..31
    const int chunk = tid & 7;        // 0..7

    for (int p = 0; p < PAIRS; p++) {
        const int ipair = item0 + p * 2;          // even -> 16B-aligned source

        // ---- issue bulk copy of the 2-item slab (one thread) ----
        if (tid == 0) {
            asm volatile("mbarrier.arrive.expect_tx.shared.b64 _, [%0], %1;"
                         :: "r"(mbar_a), "r"((uint32_t)PAIR_BYTES) : "memory");
            asm volatile(
                "cp.async.bulk.shared::cluster.global.mbarrier::complete_tx::bytes "
                "[%0], [%1], %2, [%3];"
                :: "r"(spred_a),
                   "l"(preds + (size_t)ipair * ITEMF),
                   "r"((uint32_t)PAIR_BYTES),
                   "r"(mbar_a)
                : "memory");
        }

        // ---- stage GT metadata for the pair (64 GTs, contiguous) ----
        const int gbase = ipair * NGT;
        if (tid < 64)        sbox[tid]        = __ldg((const float4*)gt_boxes + gbase + tid);
        else if (tid < 128)  slab[tid - 64]   = __ldg(gt_labels + gbase + tid - 64);
        else if (tid < 192)  svalid[tid - 128] = (__ldg(gt_valid + gbase + tid - 128) != 0) ? 1.f : 0.f;
        __syncthreads();   // GT smem visible to all

        // ---- wait for the slab ----
        {
            uint32_t done;
            asm volatile(
                "{\n\t.reg .pred q;\n\t"
                "mbarrier.try_wait.parity.acquire.cta.shared::cta.b64 q, [%1], %2;\n\t"
                "selp.b32 %0, 1, 0, q;\n\t}"
                : "=r"(done) : "r"(mbar_a), "r"((uint32_t)(p & 1)) : "memory");
            if (!done) {
                asm volatile(
                    "{\n\t.reg .pred Q;\n\t"
                    "WL_%=:\n\t"
                    "mbarrier.try_wait.parity.acquire.cta.shared::cta.b64 Q, [%0], %1, 0x989680;\n\t"
                    "@Q bra.uni WD_%=;\n\t"
                    "bra.uni WL_%=;\n\t"
                    "WD_%=:\n\t}"
                    :: "r"(mbar_a), "r"((uint32_t)(p & 1)) : "memory");
            }
        }

        // ---- Phase 1: 2 items x 32 GTs x 8 chunks of 10 logits ----
        #pragma unroll
        for (int il = 0; il < 2; il++) {
            const int g = il * 32 + gt_l;
            const float4 gb = sbox[g];
            const int   label = slab[g];
            const float mval  = svalid[g];

            const float x1 = gb.x, y1 = gb.y, x2 = gb.z, y2 = gb.w;
            const float cx = (x1 + x2) * 0.5f;
            const float cy = (y1 + y2) * 0.5f;
            const int gi = min(max((int)floorf(cx * (float)S_), 0), S_ - 1);
            const int gj = min(max((int)floorf(cy * (float)S_), 0), S_ - 1);
            const int cellbase = il * ITEMF + (gj * S_ + gi) * CELLF;

            // partial softmax over 10 class logits
            float s = 0.f, sq = 0.f, el = 0.f;
            const int lc = label - 10 * chunk;    // label's pos inside this chunk
            #pragma unroll
            for (int i = 0; i < 10; i++) {
                const float e = __expf(spred[cellbase + 10 + chunk * 10 + i]);
                s  += e;
                sq += e * e;
                if (i == lc) el = e;
            }
            // reduce across the 8 chunk lanes (contiguous lane groups)
            #pragma unroll
            for (int o = 1; o < 8; o <<= 1) {
                s  += __shfl_xor_sync(FULL, s,  o);
                sq += __shfl_xor_sync(FULL, sq, o);
                el += __shfl_xor_sync(FULL, el, o);
            }

            if (chunk == 0) {
                const float inv = 1.0f / s;
                const float cls_term = sq * inv * inv - 2.0f * el * inv + 1.0f;

                const float w = fmaxf(x2 - x1, 1e-6f);
                const float h = fmaxf(y2 - y1, 1e-6f);
                float bx[10];
                #pragma unroll
                for (int j = 0; j < 10; j++) bx[j] = spred[cellbase + j];

                const float area_g = (x2 - x1) * (y2 - y1);
                float iou[2], sxk[2], syk[2], twk[2], thk[2], tok[2];
                #pragma unroll
                for (int k = 0; k < 2; k++) {
                    const float tx = bx[k*5+0], ty = bx[k*5+1];
                    const float tw = bx[k*5+2], th = bx[k*5+3];
                    const float sx = sigmoidf_(tx);
                    const float sy = sigmoidf_(ty);
                    const float pw = tw * tw, ph = th * th;
                    const float px = (sx + (float)gi) * (1.0f / S_);
                    const float py = (sy + (float)gj) * (1.0f / S_);
                    const float px1 = px - 0.5f * pw, px2v = px + 0.5f * pw;
                    const float py1 = py - 0.5f * ph, py2v = py + 0.5f * ph;
                    const float iw = fmaxf(0.f, fminf(px2v, x2) - fmaxf(px1, x1));
                    const float ih = fmaxf(0.f, fminf(py2v, y2) - fmaxf(py1, y1));
                    const float inter = iw * ih;
                    iou[k] = inter / (pw * ph + area_g - inter + 1e-6f);
                    sxk[k] = sx; syk[k] = sy; twk[k] = tw; thk[k] = th; tok[k] = bx[k*5+4];
                }
                const int   best = (iou[1] > iou[0]) ? 1 : 0;
                const float iou_best = fmaxf(iou[0], iou[1]);

                const float so  = sigmoidf_(tok[best]);
                const float tgx = cx * (float)S_ - (float)gi;
                const float tgy = cy * (float)S_ - (float)gj;
                const float tgw = sqrtf(w), tgh = sqrtf(h);
                const float dx = sxk[best] - tgx, dy = syk[best] - tgy;
                const float dw = twk[best] - tgw, dh = thk[best] - tgh;
                const float dob = so - iou_best;

                coord   += mval * (dx*dx + dy*dy + dw*dw + dh*dh);
                obj     += mval * dob * dob;
                posconf += mval * so * so;
                npos    += mval;
                clsl    += mval * cls_term;
            }
        }

        // ---- Phase 2: all 196 conf values of the pair ----
        if (tid < 196) {
            const int il   = tid / 98;
            const int r    = tid - il * 98;
            const int cell = r >> 1;
            const int k    = r & 1;
            const float so = sigmoidf_(spred[il * ITEMF + cell * CELLF + 4 + 5 * k]);
            noobj += so * so;
        }

        __syncthreads();   // everyone done reading smem before next bulk overwrite
    }

    // ================= Block reduction -> g_part =================
    float vals[6] = {coord, obj, posconf, clsl, npos, noobj};
    #pragma unroll
    for (int j = 0; j < 6; j++) {
        #pragma unroll
        for (int o = 16; o; o >>= 1)
            vals[j] += __shfl_xor_sync(FULL, vals[j], o);
    }
    if (lane == 0) {
        #pragma unroll
        for (int j = 0; j < 6; j++) shred[wid][j] = (double)vals[j];
    }
    __syncthreads();
    if (tid < 6) {
        double acc = 0.0;
        #pragma unroll
        for (int wI = 0; wI < NWARP; wI++) acc += shred[wI][tid];
        g_part[blockIdx.x][tid] = acc;
    }

    // ================= Grid-wide finalize: last block reduces =================
    __shared__ bool is_last;
    __threadfence();
    if (tid == 0) {
        const unsigned prev = atomicAdd(&g_count, 1u);
        is_last = (prev == (unsigned)(NBLK - 1));
        if (is_last) g_count = 0u;          // reset for next graph replay
    }
    __syncthreads();
    if (!is_last) return;

    double a[6] = {0, 0, 0, 0, 0, 0};
    for (int bb = tid; bb < NBLK; bb += NTHR) {
        #pragma unroll
        for (int j = 0; j < 6; j++) a[j] += __ldcg(&g_part[bb][j]);
    }
    #pragma unroll
    for (int j = 0; j < 6; j++) {
        #pragma unroll
        for (int o = 16; o; o >>= 1)
            a[j] += __shfl_xor_sync(FULL, a[j], o);
    }
    if (lane == 0) {
        #pragma unroll
        for (int j = 0; j < 6; j++) shred[wid][j] = a[j];
    }
    __syncthreads();
    if (tid == 0) {
        double tt[6];
        #pragma unroll
        for (int j = 0; j < 6; j++) {
            tt[j] = 0.0;
            for (int wI = 0; wI < NWARP; wI++) tt[j] += shred[wI][j];
        }
        const double nposd = fmax(tt[4], 1.0);
        const double nneg  = fmax((double)NBOX - tt[4], 1.0);
        const double ncell = fmax(tt[4], 1.0);   // GT cells are distinct per batch item
        const double loss = 5.0 * tt[0] / nposd          // LC * coord
                          + tt[1] / nposd                // obj
                          + 0.5 * (tt[5] - tt[2]) / nneg // LN * noobj (all - positive)
                          + tt[3] / ncell;               // cls
        *out = (float)loss;
    }
}

extern "C" void kernel_launch(void* const* d_in, const int* in_sizes, int n_in,
                              void* d_out, int out_size)
{
    const float*         preds     = (const float*)d_in[0];
    const float*         gt_boxes  = (const float*)d_in[1];
    const int*           gt_labels = (const int*)d_in[2];
    const unsigned char* gt_valid  = (const unsigned char*)d_in[3];
    float* out = (float*)d_out;

    yolo_loss_stream<<<NBLK, NTHR>>>(preds, gt_boxes, gt_labels, gt_valid, out);
}

// round 6
// speedup vs baseline: 1.0728x; 1.0728x over previous
#include <cuda_runtime.h>
#include <math.h>
#include <float.h>
#include <stdint.h>

// Problem constants (fixed by the dataset)
#define S_   7
#define B_   2
#define C_   80
#define NGT  32
#define BT_  8192
#define CELLF 90                    // B*5 + C
#define ITEMF (S_ * S_ * CELLF)     // 4410 floats per batch item
#define NCELLS (BT_ * S_ * S_)      // 401408
#define NBOX   (NCELLS * B_)        // 802816
#define NGTS   (BT_ * NGT)          // 262144

#define NTHR 256
#define ITEMS_PER_BLOCK 8
#define PAIRS 4                          // pairs of items per block
#define NBLK (BT_ / ITEMS_PER_BLOCK)     // 1024
#define NWARP (NTHR / 32)
#define PAIR_FLOATS (2 * ITEMF)          // 8820
#define PAIR_BYTES  (PAIR_FLOATS * 4)    // 35280 (16B multiple; even-item start is 16B aligned)

// Per-block partial sums: [coord, obj, posconf_sq, cls, npos, noobj_all]
__device__ double g_part[NBLK][6];
__device__ unsigned int g_count = 0;

__device__ __forceinline__ float sigmoidf_(float x) {
    return 1.0f / (1.0f + __expf(-x));
}

__device__ __forceinline__ uint32_t smem_u32(const void* p) {
    uint32_t a;
    asm("{ .reg .u64 t; cvta.to.shared.u64 t, %1; cvt.u32.u64 %0, t; }"
        : "=r"(a) : "l"(p));
    return a;
}

__device__ __forceinline__ void mbar_wait(uint32_t addr, uint32_t parity) {
    uint32_t done;
    asm volatile(
        "{\n\t.reg .pred q;\n\t"
        "mbarrier.try_wait.parity.acquire.cta.shared::cta.b64 q, [%1], %2;\n\t"
        "selp.b32 %0, 1, 0, q;\n\t}"
        : "=r"(done) : "r"(addr), "r"(parity) : "memory");
    if (!done) {
        asm volatile(
            "{\n\t.reg .pred Q;\n\t"
            "WL_%=:\n\t"
            "mbarrier.try_wait.parity.acquire.cta.shared::cta.b64 Q, [%0], %1, 0x989680;\n\t"
            "@Q bra.uni WD_%=;\n\t"
            "bra.uni WL_%=;\n\t"
            "WD_%=:\n\t}"
            :: "r"(addr), "r"(parity) : "memory");
    }
}

__global__ void __launch_bounds__(NTHR, 3)
yolo_loss_pipe(const float* __restrict__ preds,
               const float* __restrict__ gt_boxes,
               const int* __restrict__ gt_labels,
               const unsigned char* __restrict__ gt_valid,
               float* __restrict__ out)
{
    __shared__ __align__(16) float sbuf[2][PAIR_FLOATS];   // 70,560 B
    __shared__ unsigned long long mbar[2];
    __shared__ double shred[NWARP][6];

    const int tid  = threadIdx.x;
    const int lane = tid & 31;
    const int wid  = tid >> 5;
    const unsigned FULL = 0xffffffffu;

    const uint32_t mbar_a0 = smem_u32(&mbar[0]);
    const uint32_t mbar_a1 = smem_u32(&mbar[1]);
    const uint32_t buf_a0  = smem_u32(&sbuf[0][0]);
    const uint32_t buf_a1  = smem_u32(&sbuf[1][0]);

    const int item0 = blockIdx.x * ITEMS_PER_BLOCK;

    if (tid == 0) {
        asm volatile("mbarrier.init.shared.b64 [%0], %1;" :: "r"(mbar_a0), "r"(1u) : "memory");
        asm volatile("mbarrier.init.shared.b64 [%0], %1;" :: "r"(mbar_a1), "r"(1u) : "memory");
    }
    __syncthreads();

    // Prologue: fill both buffers (pairs 0 and 1)
    if (tid == 0) {
        #pragma unroll
        for (int p = 0; p < 2; p++) {
            const uint32_t mb = p ? mbar_a1 : mbar_a0;
            const uint32_t bf = p ? buf_a1  : buf_a0;
            asm volatile("mbarrier.arrive.expect_tx.shared.b64 _, [%0], %1;"
                         :: "r"(mb), "r"((uint32_t)PAIR_BYTES) : "memory");
            asm volatile(
                "cp.async.bulk.shared::cluster.global.mbarrier::complete_tx::bytes "
                "[%0], [%1], %2, [%3];"
                :: "r"(bf), "l"(preds + (size_t)(item0 + 2 * p) * ITEMF),
                   "r"((uint32_t)PAIR_BYTES), "r"(mb)
                : "memory");
        }
    }

    float coord = 0.f, obj = 0.f, posconf = 0.f, clsl = 0.f, npos = 0.f, noobj = 0.f;

    for (int p = 0; p < PAIRS; p++) {
        const int buf = p & 1;
        const uint32_t mb = buf ? mbar_a1 : mbar_a0;
        const float* sp = sbuf[buf];

        // GT metadata (gmem, coalesced) issued BEFORE the wait to overlap copy latency
        float4 gb; int label = 0; float mval = 0.f;
        if (tid < 64) {
            const int t = (item0 + 2 * p) * NGT + tid;
            gb    = __ldg((const float4*)gt_boxes + t);
            label = __ldg(gt_labels + t);
            mval  = (__ldg(gt_valid + t) != 0) ? 1.0f : 0.0f;
        }

        mbar_wait(mb, (uint32_t)((p >> 1) & 1));

        if (tid < 64) {
            // ---------- one thread per GT, straight from smem ----------
            const float x1 = gb.x, y1 = gb.y, x2 = gb.z, y2 = gb.w;
            const float cx = (x1 + x2) * 0.5f;
            const float cy = (y1 + y2) * 0.5f;
            const float w  = fmaxf(x2 - x1, 1e-6f);
            const float h  = fmaxf(y2 - y1, 1e-6f);
            const int gi = min(max((int)floorf(cx * (float)S_), 0), S_ - 1);
            const int gj = min(max((int)floorf(cy * (float)S_), 0), S_ - 1);
            const int il = tid >> 5;                        // item within pair
            const int cb = il * ITEMF + (gj * S_ + gi) * CELLF;

            // softmax over the 80 contiguous class logits (float2 reads, 8B aligned)
            const float2* c2 = (const float2*)(sp + cb + 10);   // cb even, +10 even
            float s0 = 0.f, s1 = 0.f, q0 = 0.f, q1 = 0.f;
            #pragma unroll
            for (int i = 0; i < 40; i++) {
                const float2 v = c2[i];
                const float ea = __expf(v.x);
                const float eb = __expf(v.y);
                s0 += ea; q0 += ea * ea;
                s1 += eb; q1 += eb * eb;
            }
            const float s  = s0 + s1;
            const float sq = q0 + q1;
            const float el = __expf(sp[cb + 10 + label]);
            const float inv = 1.0f / s;
            const float cls_term = sq * inv * inv - 2.0f * el * inv + 1.0f;

            // box floats 0..9
            float bx[10];
            const float2* b2 = (const float2*)(sp + cb);
            #pragma unroll
            for (int j = 0; j < 5; j++) { bx[2*j] = b2[j].x; bx[2*j+1] = b2[j].y; }

            const float area_g = (x2 - x1) * (y2 - y1);
            float iou[2], sxk[2], syk[2], twk[2], thk[2], tok[2];
            #pragma unroll
            for (int k = 0; k < 2; k++) {
                const float tx = bx[k*5+0], ty = bx[k*5+1];
                const float tw = bx[k*5+2], th = bx[k*5+3];
                const float sx = sigmoidf_(tx);
                const float sy = sigmoidf_(ty);
                const float pw = tw * tw, ph = th * th;
                const float px = (sx + (float)gi) * (1.0f / S_);
                const float py = (sy + (float)gj) * (1.0f / S_);
                const float px1 = px - 0.5f * pw, px2v = px + 0.5f * pw;
                const float py1 = py - 0.5f * ph, py2v = py + 0.5f * ph;
                const float iw = fmaxf(0.f, fminf(px2v, x2) - fmaxf(px1, x1));
                const float ih = fmaxf(0.f, fminf(py2v, y2) - fmaxf(py1, y1));
                const float inter = iw * ih;
                iou[k] = inter / (pw * ph + area_g - inter + 1e-6f);
                sxk[k] = sx; syk[k] = sy; twk[k] = tw; thk[k] = th; tok[k] = bx[k*5+4];
            }
            const int   best = (iou[1] > iou[0]) ? 1 : 0;
            const float iou_best = fmaxf(iou[0], iou[1]);

            const float so  = sigmoidf_(tok[best]);
            const float tgx = cx * (float)S_ - (float)gi;
            const float tgy = cy * (float)S_ - (float)gj;
            const float tgw = sqrtf(w), tgh = sqrtf(h);
            const float dx = sxk[best] - tgx, dy = syk[best] - tgy;
            const float dw = twk[best] - tgw, dh = thk[best] - tgh;
            const float dob = so - iou_best;

            coord   += mval * (dx*dx + dy*dy + dw*dw + dh*dh);
            obj     += mval * dob * dob;
            posconf += mval * so * so;
            npos    += mval;
            clsl    += mval * cls_term;
        } else {
            // ---------- conf warps: 196 confs over 192 threads ----------
            int r = tid - 64;
            #pragma unroll
            for (int rep = 0; rep < 2; rep++) {
                if (rep == 0 || r + 192 < 196) {
                    const int rr   = rep ? r + 192 : r;
                    const int il   = rr / 98;
                    const int rem  = rr - il * 98;
                    const int cell = rem >> 1;
                    const int k    = rem & 1;
                    const float so = sigmoidf_(sp[il * ITEMF + cell * CELLF + 4 + 5 * k]);
                    noobj += so * so;
                }
            }
        }

        __syncthreads();   // everyone done with this buffer

        // refill this buffer with pair p+2
        if (p + 2 < PAIRS && tid == 0) {
            const uint32_t bf = buf ? buf_a1 : buf_a0;
            asm volatile("mbarrier.arrive.expect_tx.shared.b64 _, [%0], %1;"
                         :: "r"(mb), "r"((uint32_t)PAIR_BYTES) : "memory");
            asm volatile(
                "cp.async.bulk.shared::cluster.global.mbarrier::complete_tx::bytes "
                "[%0], [%1], %2, [%3];"
                :: "r"(bf), "l"(preds + (size_t)(item0 + 2 * (p + 2)) * ITEMF),
                   "r"((uint32_t)PAIR_BYTES), "r"(mb)
                : "memory");
        }
    }

    // ================= Block reduction -> g_part =================
    float vals[6] = {coord, obj, posconf, clsl, npos, noobj};
    #pragma unroll
    for (int j = 0; j < 6; j++) {
        #pragma unroll
        for (int o = 16; o; o >>= 1)
            vals[j] += __shfl_xor_sync(FULL, vals[j], o);
    }
    if (lane == 0) {
        #pragma unroll
        for (int j = 0; j < 6; j++) shred[wid][j] = (double)vals[j];
    }
    __syncthreads();
    if (tid < 6) {
        double acc = 0.0;
        #pragma unroll
        for (int wI = 0; wI < NWARP; wI++) acc += shred[wI][tid];
        g_part[blockIdx.x][tid] = acc;
    }

    // ================= Grid-wide finalize: last block reduces =================
    __shared__ bool is_last;
    __threadfence();
    if (tid == 0) {
        const unsigned prev = atomicAdd(&g_count, 1u);
        is_last = (prev == (unsigned)(NBLK - 1));
        if (is_last) g_count = 0u;          // reset for next graph replay
    }
    __syncthreads();
    if (!is_last) return;

    double a[6] = {0, 0, 0, 0, 0, 0};
    for (int bb = tid; bb < NBLK; bb += NTHR) {
        #pragma unroll
        for (int j = 0; j < 6; j++) a[j] += __ldcg(&g_part[bb][j]);
    }
    #pragma unroll
    for (int j = 0; j < 6; j++) {
        #pragma unroll
        for (int o = 16; o; o >>= 1)
            a[j] += __shfl_xor_sync(FULL, a[j], o);
    }
    if (lane == 0) {
        #pragma unroll
        for (int j = 0; j < 6; j++) shred[wid][j] = a[j];
    }
    __syncthreads();
    if (tid == 0) {
        double tt[6];
        #pragma unroll
        for (int j = 0; j < 6; j++) {
            tt[j] = 0.0;
            for (int wI = 0; wI < NWARP; wI++) tt[j] += shred[wI][j];
        }
        const double nposd = fmax(tt[4], 1.0);
        const double nneg  = fmax((double)NBOX - tt[4], 1.0);
        const double ncell = fmax(tt[4], 1.0);   // GT cells are distinct per batch item
        const double loss = 5.0 * tt[0] / nposd          // LC * coord
                          + tt[1] / nposd                // obj
                          + 0.5 * (tt[5] - tt[2]) / nneg // LN * noobj (all - positive)
                          + tt[3] / ncell;               // cls
        *out = (float)loss;
    }
}

extern "C" void kernel_launch(void* const* d_in, const int* in_sizes, int n_in,
                              void* d_out, int out_size)
{
    const float*         preds     = (const float*)d_in[0];
    const float*         gt_boxes  = (const float*)d_in[1];
    const int*           gt_labels = (const int*)d_in[2];
    const unsigned char* gt_valid  = (const unsigned char*)d_in[3];
    float* out = (float*)d_out;

    yolo_loss_pipe<<<NBLK, NTHR>>>(preds, gt_boxes, gt_labels, gt_valid, out);
}

// round 7
// speedup vs baseline: 1.1288x; 1.0522x over previous
#include <cuda_runtime.h>
#include <math.h>
#include <float.h>

// Problem constants (fixed by the dataset)
#define S_   7
#define B_   2
#define C_   80
#define NGT  32
#define BT_  8192
#define CELLF 90                    // B*5 + C
#define NCELLS (BT_ * S_ * S_)      // 401408
#define NBOX   (NCELLS * B_)        // 802816
#define NGTS   (BT_ * NGT)          // 262144

#define NTHR 128
#define NBLK (NGTS / NTHR)          // 2048 blocks -> exactly 1 GT per thread
#define NTOT (NBLK * NTHR)          // 262144
#define NWARP (NTHR / 32)           // 4

// Per-block partial sums: [coord, obj, posconf_sq, cls, npos, noobj_all]
__device__ double g_part[NBLK][6];
__device__ unsigned int g_count = 0;

__device__ __forceinline__ float sigmoidf_(float x) {
    return 1.0f / (1.0f + __expf(-x));
}

__global__ void __launch_bounds__(NTHR, 10)
yolo_loss_fused(const float* __restrict__ preds,
                const float* __restrict__ gt_boxes,
                const int* __restrict__ gt_labels,
                const unsigned char* __restrict__ gt_valid,
                float* __restrict__ out)
{
    const int tid  = threadIdx.x;
    const int lane = tid & 31;
    const int wid  = tid >> 5;
    const int t    = blockIdx.x * NTHR + tid;      // GT index, exact
    const unsigned FULL = 0xffffffffu;

    float coord, obj, posconf, clsl, npos, noobj = 0.f;

    // ================= Phase 1: one THREAD per GT =================
    {
        const float mval = (__ldg(gt_valid + t) != 0) ? 1.0f : 0.0f;
        const float4 gb  = __ldg((const float4*)gt_boxes + t);
        const int   label = __ldg(gt_labels + t);

        const float x1 = gb.x, y1 = gb.y, x2 = gb.z, y2 = gb.w;
        const float cx = (x1 + x2) * 0.5f;
        const float cy = (y1 + y2) * 0.5f;
        const float w  = fmaxf(x2 - x1, 1e-6f);
        const float h  = fmaxf(y2 - y1, 1e-6f);
        const int gi = min(max((int)floorf(cx * (float)S_), 0), S_ - 1);
        const int gj = min(max((int)floorf(cy * (float)S_), 0), S_ - 1);

        const int  b       = t >> 5;                       // t / NGT
        const int  cellIdx = b * (S_ * S_) + gj * S_ + gi;
        const float* cell  = preds + (size_t)cellIdx * CELLF;

        // label-logit gather (independent scalar load, overlaps everything)
        const float cl = __ldg(cell + 10 + label);

        // 16B-aligned vec4 view: off = 0 (even cell) or 2 floats (odd cell)
        const int   off  = (cellIdx & 1) << 1;             // 0 or 2
        const float msh  = (float)(off >> 1);              // 1.0 if shifted
        const float mns  = 1.0f - msh;                     // 1.0 if not shifted
        const float4* v4 = (const float4*)(cell - off);

        // ---- head: loaded positions 0..11 ----
        float p[12];
        {
            const float4 a  = __ldg(v4 + 0);
            const float4 bq = __ldg(v4 + 1);
            const float4 c  = __ldg(v4 + 2);
            p[0]=a.x;  p[1]=a.y;  p[2]=a.z;  p[3]=a.w;
            p[4]=bq.x; p[5]=bq.y; p[6]=bq.z; p[7]=bq.w;
            p[8]=c.x;  p[9]=c.y;  p[10]=c.z; p[11]=c.w;
        }
        float bx[10];
        #pragma unroll
        for (int j = 0; j < 10; j++) bx[j] = (off != 0) ? p[j + 2] : p[j];

        // off=0: positions 10,11 are class logits 10,11 (else box floats)
        const float e10 = __expf(p[10]);
        const float e11 = __expf(p[11]);
        float s0 = mns * (e10 + e11),          s1 = 0.f, s2 = 0.f, s3 = 0.f;
        float q0 = mns * (e10*e10 + e11*e11),  q1 = 0.f, q2 = 0.f, q3 = 0.f;

        // ---- body: positions 12..91 (vec 3..22) in 4 chunks of 5 vec4 ----
        #pragma unroll
        for (int ch = 0; ch < 4; ch++) {
            float4 u0 = __ldg(v4 + 3 + ch*5 + 0);
            float4 u1 = __ldg(v4 + 3 + ch*5 + 1);
            float4 u2 = __ldg(v4 + 3 + ch*5 + 2);
            float4 u3 = __ldg(v4 + 3 + ch*5 + 3);
            float4 u4 = __ldg(v4 + 3 + ch*5 + 4);
            float q[20] = {u0.x,u0.y,u0.z,u0.w, u1.x,u1.y,u1.z,u1.w,
                           u2.x,u2.y,u2.z,u2.w, u3.x,u3.y,u3.z,u3.w,
                           u4.x,u4.y,u4.z,u4.w};
            #pragma unroll
            for (int i = 0; i < 20; i++) {
                float e = __expf(q[i]);
                if (ch == 3 && i >= 18) e *= msh;   // 90,91 valid only when off=2
                if      ((i & 3) == 0) { s0 += e; q0 += e*e; }
                else if ((i & 3) == 1) { s1 += e; q1 += e*e; }
                else if ((i & 3) == 2) { s2 += e; q2 += e*e; }
                else                   { s3 += e; q3 += e*e; }
            }
        }
        const float s  = (s0 + s1) + (s2 + s3);
        const float sq = (q0 + q1) + (q2 + q3);
        const float el = __expf(cl);
        const float inv = 1.0f / s;
        const float cls_term = sq * inv * inv - 2.0f * el * inv + 1.0f;

        // ---- IoU over both candidate boxes ----
        const float area_g = (x2 - x1) * (y2 - y1);
        float iou[2], sxk[2], syk[2], twk[2], thk[2], tok[2];
        #pragma unroll
        for (int k = 0; k < 2; k++) {
            const float tx = bx[k*5+0], ty = bx[k*5+1];
            const float tw = bx[k*5+2], th = bx[k*5+3];
            const float sx = sigmoidf_(tx);
            const float sy = sigmoidf_(ty);
            const float pw = tw * tw, ph = th * th;
            const float px = (sx + (float)gi) * (1.0f / S_);
            const float py = (sy + (float)gj) * (1.0f / S_);
            const float px1 = px - 0.5f * pw, px2v = px + 0.5f * pw;
            const float py1 = py - 0.5f * ph, py2v = py + 0.5f * ph;
            const float iw = fmaxf(0.f, fminf(px2v, x2) - fmaxf(px1, x1));
            const float ih = fmaxf(0.f, fminf(py2v, y2) - fmaxf(py1, y1));
            const float inter = iw * ih;
            iou[k] = inter / (pw * ph + area_g - inter + 1e-6f);
            sxk[k] = sx; syk[k] = sy; twk[k] = tw; thk[k] = th; tok[k] = bx[k*5+4];
        }
        const int   best = (iou[1] > iou[0]) ? 1 : 0;
        const float iou_best = fmaxf(iou[0], iou[1]);

        const float so  = sigmoidf_(tok[best]);
        const float tgx = cx * (float)S_ - (float)gi;
        const float tgy = cy * (float)S_ - (float)gj;
        const float tgw = sqrtf(w), tgh = sqrtf(h);
        const float dx = sxk[best] - tgx, dy = syk[best] - tgy;
        const float dw = twk[best] - tgw, dh = thk[best] - tgh;
        const float dob = so - iou_best;

        coord   = mval * (dx*dx + dy*dy + dw*dw + dh*dh);
        obj     = mval * dob * dob;
        posconf = mval * so * so;
        npos    = mval;
        clsl    = mval * cls_term;
    }

    // ================= Phase 2: conf over ALL cells (grid-stride, <=2) =================
    for (int c = t; c < NCELLS; c += NTOT) {
        const float* base = preds + (size_t)c * CELLF;
        const float so0 = sigmoidf_(__ldg(base + 4));
        const float so1 = sigmoidf_(__ldg(base + 9));
        noobj += so0 * so0 + so1 * so1;
    }

    // ================= Block reduction -> g_part =================
    float vals[6] = {coord, obj, posconf, clsl, npos, noobj};
    #pragma unroll
    for (int j = 0; j < 6; j++) {
        #pragma unroll
        for (int o = 16; o; o >>= 1)
            vals[j] += __shfl_xor_sync(FULL, vals[j], o);
    }
    __shared__ double sh[NWARP][6];
    if (lane == 0) {
        #pragma unroll
        for (int j = 0; j < 6; j++) sh[wid][j] = (double)vals[j];
    }
    __syncthreads();
    if (tid < 6) {
        double acc = 0.0;
        #pragma unroll
        for (int wI = 0; wI < NWARP; wI++) acc += sh[wI][tid];
        g_part[blockIdx.x][tid] = acc;
    }

    // ================= Grid-wide finalize: last block reduces =================
    __shared__ bool is_last;
    __threadfence();
    if (tid == 0) {
        const unsigned prev = atomicAdd(&g_count, 1u);
        is_last = (prev == (unsigned)(NBLK - 1));
        if (is_last) g_count = 0u;          // reset for next graph replay
    }
    __syncthreads();
    if (!is_last) return;

    double a[6] = {0, 0, 0, 0, 0, 0};
    for (int bb = tid; bb < NBLK; bb += NTHR) {
        #pragma unroll
        for (int j = 0; j < 6; j++) a[j] += __ldcg(&g_part[bb][j]);
    }
    #pragma unroll
    for (int j = 0; j < 6; j++) {
        #pragma unroll
        for (int o = 16; o; o >>= 1)
            a[j] += __shfl_xor_sync(FULL, a[j], o);
    }
    __shared__ double shf[NWARP][6];
    if (lane == 0) {
        #pragma unroll
        for (int j = 0; j < 6; j++) shf[wid][j] = a[j];
    }
    __syncthreads();
    if (tid == 0) {
        double tt[6];
        #pragma unroll
        for (int j = 0; j < 6; j++) {
            tt[j] = 0.0;
            for (int wI = 0; wI < NWARP; wI++) tt[j] += shf[wI][j];
        }
        const double nposd = fmax(tt[4], 1.0);
        const double nneg  = fmax((double)NBOX - tt[4], 1.0);
        const double ncell = fmax(tt[4], 1.0);   // GT cells are distinct per batch item
        const double loss = 5.0 * tt[0] / nposd          // LC * coord
                          + tt[1] / nposd                // obj
                          + 0.5 * (tt[5] - tt[2]) / nneg // LN * noobj (all - positive)
                          + tt[3] / ncell;               // cls
        *out = (float)loss;
    }
}

extern "C" void kernel_launch(void* const* d_in, const int* in_sizes, int n_in,
                              void* d_out, int out_size)
{
    const float*         preds     = (const float*)d_in[0];
    const float*         gt_boxes  = (const float*)d_in[1];
    const int*           gt_labels = (const int*)d_in[2];
    const unsigned char* gt_valid  = (const unsigned char*)d_in[3];
    float* out = (float*)d_out;

    yolo_loss_fused<<<NBLK, NTHR>>>(preds, gt_boxes, gt_labels, gt_valid, out);
}